// round 13
// baseline (speedup 1.0000x reference)
#include <cuda_runtime.h>
#include <cuda_bf16.h>
#include <cuda_fp16.h>
#include <cstdint>

// ---------------------------------------------------------------------------
// MatchingNetwork — Round 13: 2-TERM fp16 HMMA GEMM.
//   xh = round(x*2^11)/2^11  (EXACT in fp16; dropped residual |xl| <= 2^-12)
//   w  = wh + wl             (two fp16, ~22-bit capture)
//   sup = xh*wh + xh*wl  (= xh*w; dropped term xl*w ~ 1.2e-4 rel)
// 2/3 the MMA count of the 3-term bf16 kernel; A smem/fill work halved.
// ---------------------------------------------------------------------------

#define B_SZ   256
#define S_SZ   20
#define V_SZ   20000
#define C_SZ   20
#define D_SZ   64
#define M_SUP  (B_SZ * S_SZ)      // 5120
#define M_ALL  (M_SUP + B_SZ)     // 5376
#define KSPLIT 7
#define PITCH  176u               // smem row pitch bytes (80 fp16 = 160B + pad)

#define OF_AHI 0u
#define OF_BHI 22528u             // 128*176
#define OF_BLO 33792u             // +64*176
#define SMEM_TOTAL 45056

typedef uint32_t u32;

// ---- device scratch ---------------------------------------------------------
__device__ float  g_part[(size_t)KSPLIT * M_ALL * D_SZ];
__device__ float  g_sup[(size_t)M_ALL * D_SZ];
__device__ __half g_Whf[(size_t)D_SZ * V_SZ];
__device__ __half g_Wlf[(size_t)D_SZ * V_SZ];
__device__ float  g_pb[2 * B_SZ];

// ---- PTX helpers ------------------------------------------------------------
__device__ __forceinline__ u32 smem_u32(const void* p) {
    u32 a;
    asm("{ .reg .u64 t; cvta.to.shared.u64 t, %1; cvt.u32.u64 %0, t; }"
        : "=r"(a) : "l"(p));
    return a;
}
__device__ __forceinline__ void sts32(u32 a, u32 v) {
    asm volatile("st.shared.b32 [%0], %1;" :: "r"(a), "r"(v));
}
__device__ __forceinline__ void cp16(u32 s, const void* g) {
    asm volatile("cp.async.cg.shared.global [%0], [%1], 16;" :: "r"(s), "l"(g));
}
#define CP_COMMIT() asm volatile("cp.async.commit_group;" ::: "memory")
#define CP_WAIT0()  asm volatile("cp.async.wait_group 0;" ::: "memory")

__device__ __forceinline__ void ldm4(u32 a, u32 r[4]) {
    asm volatile("ldmatrix.sync.aligned.m8n8.x4.shared.b16 {%0,%1,%2,%3}, [%4];"
        : "=r"(r[0]), "=r"(r[1]), "=r"(r[2]), "=r"(r[3]) : "r"(a));
}
__device__ __forceinline__ void mma16816(float c[4], const u32 a[4],
                                         const u32* b) {
    asm volatile("mma.sync.aligned.m16n8k16.row.col.f32.f16.f16.f32 "
        "{%0,%1,%2,%3}, {%4,%5,%6,%7}, {%8,%9}, {%0,%1,%2,%3};"
        : "+f"(c[0]), "+f"(c[1]), "+f"(c[2]), "+f"(c[3])
        : "r"(a[0]), "r"(a[1]), "r"(a[2]), "r"(a[3]), "r"(b[0]), "r"(b[1]));
}
// quantize float2 -> packed fp16x2 of round(x*2048)*2^-11 (exact fixed-point)
__device__ __forceinline__ u32 fixq2(float2 v) {
    u32 r;
    const __half2 s = __floats2half2_rn(4.8828125e-4f, 4.8828125e-4f); // 2^-11
    __half2 h = __floats2half2_rn(v.x * 2048.f, v.y * 2048.f);         // exact ints
    h = __hmul2(h, s);                                                 // exact shift
    r = *reinterpret_cast<u32*>(&h);
    return r;
}

// ---- K0: split W into fp16 hi/lo -----------------------------------------------
__global__ void prep_w_kernel(const float* __restrict__ W) {
    int idx = blockIdx.x * 256 + threadIdx.x;          // covers D*V exactly
    float x  = W[idx];
    __half h = __float2half_rn(x);
    g_Whf[idx] = h;
    g_Wlf[idx] = __float2half_rn(x - __half2float(h));
}

// ---- K1: 2-term fp16 HMMA GEMM ---------------------------------------------------
// grid = (42 m-tiles, 7 k-slices), 128 threads (4 warps, warp tile m32 x n64)
__global__ __launch_bounds__(128) void gemm_kernel(
    const float* __restrict__ img, const float* __restrict__ tgtim)
{
    extern __shared__ char smem[];
    const u32 sb = smem_u32(smem);
    const int tid  = threadIdx.x;
    const int w    = tid >> 5;
    const int lane = tid & 31;
    const int row0 = blockIdx.x * 128;
    const int ks   = blockIdx.y;

    // k-slice in k16 steps: 1250 total -> 4x179 + 3x178
    const int sbeg = ks * 178 + (ks < 4 ? ks : 4);
    const int scnt = 178 + (ks < 4 ? 1 : 0);
    const int NCH  = (scnt + 4) / 5;                    // 36 chunks of <=5 steps

    const float* abase = (blockIdx.x < 40)
        ? img   + (size_t)row0 * V_SZ
        : tgtim + (size_t)(row0 - M_SUP) * V_SZ;

    // A fill mapping: 8 passes of 16 rows; 8 threads/row, 5 float2 each
    const int arow_l = tid >> 3;        // 0..15 (+16*pass)
    const int atc    = tid & 7;
    // B fill mapping: 2 threads/row, 5 x 16B each per array
    const int brow   = tid >> 1;        // 0..63
    const int bhalf  = tid & 1;

    // ldmatrix lane base addresses
    const u32 aLB = (u32)(w * 32 + (lane & 15)) * PITCH
                  + (u32)((lane >> 4) * 16);
    const u32 bLB = (u32)((lane & 7) + ((lane >> 4) & 1) * 8) * PITCH
                  + (u32)(((lane >> 3) & 1) * 16);

    float acc[2][8][4];
    #pragma unroll
    for (int mt = 0; mt < 2; ++mt)
        #pragma unroll
        for (int nt = 0; nt < 8; ++nt)
            #pragma unroll
            for (int i = 0; i < 4; ++i) acc[mt][nt][i] = 0.f;

    for (int c = 0; c < NCH; ++c) {
        const int nk = min(5, scnt - c * 5);            // k16 steps this chunk
        const int k0 = (sbeg + c * 5) * 16;             // element offset

        __syncthreads();                                 // smem free to refill

        // ---- B tiles via cp.async (fp16 hi/lo pre-split in gmem) ----
        {
            const char* gh = (const char*)(g_Whf + (size_t)brow * V_SZ + k0);
            const char* gl = (const char*)(g_Wlf + (size_t)brow * V_SZ + k0);
            u32 sB = sb + (u32)brow * PITCH;
            #pragma unroll
            for (int j = 0; j < 5; ++j) {
                int piece = bhalf * 5 + j;
                if (piece < 2 * nk) {
                    cp16(sB + OF_BHI + piece * 16, gh + piece * 16);
                    cp16(sB + OF_BLO + piece * 16, gl + piece * 16);
                }
            }
            CP_COMMIT();
        }

        // ---- A tiles: LDG fp32 -> exact fixed-point fp16 -> STS ----
        #pragma unroll
        for (int p = 0; p < 8; ++p) {
            const int rl = arow_l + p * 16;
            const float2* rp = (const float2*)(abase + (size_t)rl * V_SZ + k0);
            u32 sA = sb + (u32)rl * PITCH;
            #pragma unroll
            for (int j = 0; j < 5; ++j) {
                if (j < nk) {
                    const int c2 = j * 8 + atc;          // float2 index
                    sts32(sA + OF_AHI + c2 * 4, fixq2(rp[c2]));
                }
            }
        }

        CP_WAIT0();
        __syncthreads();

        // ---- MMA over nk k16-steps: hoisted loads, term-major de-chained ----
        for (int s = 0; s < nk; ++s) {
            const u32 sbyte = (u32)s * 32;
            u32 ah[2][4];
            #pragma unroll
            for (int mt = 0; mt < 2; ++mt)
                ldm4(sb + aLB + (u32)mt * (16 * PITCH) + sbyte + OF_AHI, ah[mt]);
            u32 bh[4][4], bl[4][4];
            #pragma unroll
            for (int q = 0; q < 4; ++q) {
                u32 a = sb + bLB + (u32)q * (16 * PITCH) + sbyte;
                ldm4(a + OF_BHI, bh[q]);
                ldm4(a + OF_BLO, bl[q]);
            }
            // term 1: Xh * Wh — 16 distinct accumulators
            #pragma unroll
            for (int q = 0; q < 4; ++q)
                #pragma unroll
                for (int mt = 0; mt < 2; ++mt)
                    #pragma unroll
                    for (int h = 0; h < 2; ++h)
                        mma16816(acc[mt][q * 2 + h], ah[mt], &bh[q][2 * h]);
            // term 2: Xh * Wl
            #pragma unroll
            for (int q = 0; q < 4; ++q)
                #pragma unroll
                for (int mt = 0; mt < 2; ++mt)
                    #pragma unroll
                    for (int h = 0; h < 2; ++h)
                        mma16816(acc[mt][q * 2 + h], ah[mt], &bl[q][2 * h]);
        }
    }

    // ---- epilogue: store partials ----
    const int r4 = lane >> 2, c4 = lane & 3;
    #pragma unroll
    for (int mt = 0; mt < 2; ++mt) {
        const size_t rg = (size_t)row0 + w * 32 + mt * 16 + r4;
        float* base = &g_part[((size_t)ks * M_ALL + rg) * D_SZ];
        #pragma unroll
        for (int nt = 0; nt < 8; ++nt) {
            float2 v0 = make_float2(acc[mt][nt][0], acc[mt][nt][1]);
            float2 v1 = make_float2(acc[mt][nt][2], acc[mt][nt][3]);
            *(float2*)(base + nt * 8 + c4 * 2)                 = v0;
            *(float2*)(base + 8 * (size_t)D_SZ + nt * 8 + c4 * 2) = v1;
        }
    }
}

// ---- K2: reduce k-slices + bias -> g_sup --------------------------------------
__global__ void reduce_kernel(const float* __restrict__ bias) {
    int idx = blockIdx.x * 256 + threadIdx.x;          // covers M_ALL*D exactly
    float s = bias[idx & 63];
    #pragma unroll
    for (int ks = 0; ks < KSPLIT; ++ks)
        s += g_part[(size_t)ks * M_ALL * D_SZ + idx];
    g_sup[idx] = s;
}

// ---- K3: warp-per-episode sims/softmax/preds/argmax/CE ------------------------
__global__ void sim_kernel(const float* __restrict__ onehot,
                           const int* __restrict__ tgty)
{
    const int b    = blockIdx.x;                    // 256 blocks, 32 threads
    const int lane = threadIdx.x;
    const unsigned FULL = 0xFFFFFFFFu;

    const float4* t4 = (const float4*)&g_sup[(size_t)(M_SUP + b) * D_SZ];
    float sim = -3.0e38f;
    if (lane < S_SZ) {
        const float4* s4 = (const float4*)&g_sup[(size_t)(b * S_SZ + lane) * D_SZ];
        float d0 = 0.f, d1 = 0.f, d2 = 0.f, d3 = 0.f;
        float m0 = 0.f, m1 = 0.f, m2 = 0.f, m3 = 0.f;
        #pragma unroll
        for (int i = 0; i < 16; ++i) {
            float4 s = s4[i], t = t4[i];
            d0 += s.x * t.x; d1 += s.y * t.y; d2 += s.z * t.z; d3 += s.w * t.w;
            m0 += s.x * s.x; m1 += s.y * s.y; m2 += s.z * s.z; m3 += s.w * s.w;
        }
        float dot = (d0 + d1) + (d2 + d3);
        float mag = (m0 + m1) + (m2 + m3);
        sim = dot * rsqrtf(fmaxf(mag, 1e-10f));
    }
    float m = sim;
    #pragma unroll
    for (int o = 16; o; o >>= 1) m = fmaxf(m, __shfl_xor_sync(FULL, m, o));
    float e = (lane < S_SZ) ? expf(sim - m) : 0.f;
    float sum = e;
    #pragma unroll
    for (int o = 16; o; o >>= 1) sum += __shfl_xor_sync(FULL, sum, o);
    float attn = e / sum;

    float p = 0.f;
    #pragma unroll
    for (int s = 0; s < S_SZ; ++s) {
        float a = __shfl_sync(FULL, attn, s);
        if (lane < C_SZ) p += a * onehot[((size_t)b * S_SZ + s) * C_SZ + lane];
    }

    float bv = (lane < C_SZ) ? p : -3.0e38f;
    int   bi = (lane < C_SZ) ? lane : 999;
    #pragma unroll
    for (int o = 16; o; o >>= 1) {
        float ov = __shfl_xor_sync(FULL, bv, o);
        int   oi = __shfl_xor_sync(FULL, bi, o);
        if (ov > bv || (ov == bv && oi < bi)) { bv = ov; bi = oi; }
    }
    float pm = (lane < C_SZ) ? p : -3.0e38f;
    #pragma unroll
    for (int o = 16; o; o >>= 1) pm = fmaxf(pm, __shfl_xor_sync(FULL, pm, o));
    float ee = (lane < C_SZ) ? expf(p - pm) : 0.f;
    float lse = ee;
    #pragma unroll
    for (int o = 16; o; o >>= 1) lse += __shfl_xor_sync(FULL, lse, o);

    int y = tgty[b];
    float py = __shfl_sync(FULL, p, y);
    if (lane == 0) {
        g_pb[b]        = (bi == y) ? 1.f : 0.f;
        g_pb[B_SZ + b] = -(py - pm - logf(lse));
    }
}

// ---- K4: deterministic final reduction -> d_out -------------------------------
__global__ void finalize_kernel(float* __restrict__ out) {
    __shared__ float sc[B_SZ], sl[B_SZ];
    int t = threadIdx.x;
    sc[t] = g_pb[t];
    sl[t] = g_pb[B_SZ + t];
    __syncthreads();
    for (int off = 128; off > 0; off >>= 1) {
        if (t < off) { sc[t] += sc[t + off]; sl[t] += sl[t + off]; }
        __syncthreads();
    }
    if (t == 0) {
        out[0] = sc[0] * (1.f / (float)B_SZ);
        out[1] = sl[0] * (1.f / (float)B_SZ);
    }
}

// ---------------------------------------------------------------------------
extern "C" void kernel_launch(void* const* d_in, const int* in_sizes, int n_in,
                              void* d_out, int out_size)
{
    const float* img    = (const float*)d_in[0];   // [256,20,20000]
    const float* onehot = (const float*)d_in[1];   // [256,20,20]
    const float* tgtim  = (const float*)d_in[2];   // [256,20000]
    const int*   tgty   = (const int*)  d_in[3];   // [256]
    const float* W      = (const float*)d_in[4];   // [64,20000]
    const float* bias   = (const float*)d_in[5];   // [64]
    float* out = (float*)d_out;                    // [2]

    cudaFuncSetAttribute(gemm_kernel,
                         cudaFuncAttributeMaxDynamicSharedMemorySize, SMEM_TOTAL);

    prep_w_kernel<<<(D_SZ * V_SZ) / 256, 256>>>(W);
    gemm_kernel<<<dim3(M_ALL / 128, KSPLIT), 128, SMEM_TOTAL>>>(img, tgtim);
    reduce_kernel<<<(M_ALL * D_SZ) / 256, 256>>>(bias);
    sim_kernel<<<B_SZ, 32>>>(onehot, tgty);
    finalize_kernel<<<1, B_SZ>>>(out);
}

// round 14
// speedup vs baseline: 1.3773x; 1.3773x over previous
#include <cuda_runtime.h>
#include <cuda_bf16.h>
#include <cstdint>

// ---------------------------------------------------------------------------
// MatchingNetwork — Round 14: R12 (3-term split-bf16, de-chained) with
// 8 warps/CTA (4x2, warp tile m32 x n32) -> 4 warps per SMSP, testing whether
// the ~21.4 cyc/HMMA rate is per-warp issue-limited or a pipe ceiling.
// ---------------------------------------------------------------------------

#define B_SZ   256
#define S_SZ   20
#define V_SZ   20000
#define C_SZ   20
#define D_SZ   64
#define M_SUP  (B_SZ * S_SZ)      // 5120
#define M_ALL  (M_SUP + B_SZ)     // 5376
#define KSPLIT 7
#define PITCH  176u               // smem row pitch bytes

#define OF_AHI 0u
#define OF_ALO 22528u             // 128*176
#define OF_BHI 45056u
#define OF_BLO 56320u
#define SMEM_TOTAL 67584

typedef uint32_t u32;

// ---- device scratch ---------------------------------------------------------
__device__ float         g_part[(size_t)KSPLIT * M_ALL * D_SZ];
__device__ float         g_sup[(size_t)M_ALL * D_SZ];
__device__ __nv_bfloat16 g_Whi[(size_t)D_SZ * V_SZ];
__device__ __nv_bfloat16 g_Wlo[(size_t)D_SZ * V_SZ];
__device__ float         g_pb[2 * B_SZ];

// ---- PTX helpers ------------------------------------------------------------
__device__ __forceinline__ u32 smem_u32(const void* p) {
    u32 a;
    asm("{ .reg .u64 t; cvta.to.shared.u64 t, %1; cvt.u32.u64 %0, t; }"
        : "=r"(a) : "l"(p));
    return a;
}
__device__ __forceinline__ void sts32(u32 a, u32 v) {
    asm volatile("st.shared.b32 [%0], %1;" :: "r"(a), "r"(v));
}
__device__ __forceinline__ u32 cvt2bf(float lo, float hi) {
    u32 r;
    asm("cvt.rn.bf16x2.f32 %0, %1, %2;" : "=r"(r) : "f"(hi), "f"(lo));
    return r;
}
__device__ __forceinline__ void cp16(u32 s, const void* g) {
    asm volatile("cp.async.cg.shared.global [%0], [%1], 16;" :: "r"(s), "l"(g));
}
#define CP_COMMIT() asm volatile("cp.async.commit_group;" ::: "memory")
#define CP_WAIT0()  asm volatile("cp.async.wait_group 0;" ::: "memory")

__device__ __forceinline__ void ldm4(u32 a, u32 r[4]) {
    asm volatile("ldmatrix.sync.aligned.m8n8.x4.shared.b16 {%0,%1,%2,%3}, [%4];"
        : "=r"(r[0]), "=r"(r[1]), "=r"(r[2]), "=r"(r[3]) : "r"(a));
}
__device__ __forceinline__ void mma16816(float c[4], const u32 a[4],
                                         const u32* b) {
    asm volatile("mma.sync.aligned.m16n8k16.row.col.f32.bf16.bf16.f32 "
        "{%0,%1,%2,%3}, {%4,%5,%6,%7}, {%8,%9}, {%0,%1,%2,%3};"
        : "+f"(c[0]), "+f"(c[1]), "+f"(c[2]), "+f"(c[3])
        : "r"(a[0]), "r"(a[1]), "r"(a[2]), "r"(a[3]), "r"(b[0]), "r"(b[1]));
}

// ---- K0: split W into bf16 hi/lo ---------------------------------------------
__global__ void prep_w_kernel(const float* __restrict__ W) {
    int idx = blockIdx.x * 256 + threadIdx.x;          // covers D*V exactly
    float x  = W[idx];
    __nv_bfloat16 h = __float2bfloat16_rn(x);
    g_Whi[idx] = h;
    g_Wlo[idx] = __float2bfloat16_rn(x - __bfloat162float(h));
}

// ---- K1: split-bf16 HMMA GEMM, 8 warps (4x2), de-chained -----------------------
// grid = (42 m-tiles, 7 k-slices), 256 threads; warp tile m32 x n32
__global__ __launch_bounds__(256) void gemm_kernel(
    const float* __restrict__ img, const float* __restrict__ tgtim)
{
    extern __shared__ char smem[];
    const u32 sb = smem_u32(smem);
    const int tid  = threadIdx.x;
    const int w    = tid >> 5;
    const int lane = tid & 31;
    const int wm   = w >> 1;            // 0..3 : m32 block
    const int wn   = w & 1;             // 0..1 : n32 block
    const int row0 = blockIdx.x * 128;
    const int ks   = blockIdx.y;

    // k-slice in k16 steps: 1250 total -> 4x179 + 3x178
    const int sbeg = ks * 178 + (ks < 4 ? ks : 4);
    const int scnt = 178 + (ks < 4 ? 1 : 0);
    const int NCH  = (scnt + 4) / 5;                    // 36 chunks of <=5 steps

    const float* abase = (blockIdx.x < 40)
        ? img   + (size_t)row0 * V_SZ
        : tgtim + (size_t)(row0 - M_SUP) * V_SZ;

    // A fill mapping: 4 passes of 32 rows; 8 threads/row, 5 float2 each
    const int arow_l = tid >> 3;        // 0..31 (+32*pass)
    const int atc    = tid & 7;
    // B fill mapping: 4 threads/row, pieces q+4j (j<3), 10 pieces per array
    const int brow   = tid >> 2;        // 0..63
    const int bq     = tid & 3;

    // ldmatrix lane base addresses
    const u32 aLB = (u32)(wm * 32 + (lane & 15)) * PITCH
                  + (u32)((lane >> 4) * 16);
    const u32 bLB = (u32)(wn * 32 + (lane & 7) + ((lane >> 4) & 1) * 8) * PITCH
                  + (u32)(((lane >> 3) & 1) * 16);

    float acc[2][4][4];
    #pragma unroll
    for (int mt = 0; mt < 2; ++mt)
        #pragma unroll
        for (int nt = 0; nt < 4; ++nt)
            #pragma unroll
            for (int i = 0; i < 4; ++i) acc[mt][nt][i] = 0.f;

    for (int c = 0; c < NCH; ++c) {
        const int nk = min(5, scnt - c * 5);            // k16 steps this chunk
        const int k0 = (sbeg + c * 5) * 16;             // element offset

        __syncthreads();                                 // smem free to refill

        // ---- B tiles via cp.async (bf16 hi/lo pre-split in gmem) ----
        {
            const char* gh = (const char*)(g_Whi + (size_t)brow * V_SZ + k0);
            const char* gl = (const char*)(g_Wlo + (size_t)brow * V_SZ + k0);
            u32 sB = sb + (u32)brow * PITCH;
            #pragma unroll
            for (int j = 0; j < 3; ++j) {
                int piece = bq + 4 * j;
                if (piece < 10 && piece < 2 * nk) {
                    cp16(sB + OF_BHI + piece * 16, gh + piece * 16);
                    cp16(sB + OF_BLO + piece * 16, gl + piece * 16);
                }
            }
            CP_COMMIT();
        }

        // ---- A tiles: LDG fp32 -> split bf16 hi/lo -> STS ----
        #pragma unroll
        for (int p = 0; p < 4; ++p) {
            const int rl = arow_l + p * 32;
            const float2* rp = (const float2*)(abase + (size_t)rl * V_SZ + k0);
            u32 sA = sb + (u32)rl * PITCH;
            #pragma unroll
            for (int j = 0; j < 5; ++j) {
                if (j < nk) {
                    const int c2 = j * 8 + atc;          // float2 index
                    float2 v = rp[c2];
                    u32 h = cvt2bf(v.x, v.y);
                    float r0 = v.x - __uint_as_float(h << 16);
                    float r1 = v.y - __uint_as_float(h & 0xFFFF0000u);
                    u32 l = cvt2bf(r0, r1);
                    sts32(sA + OF_AHI + c2 * 4, h);
                    sts32(sA + OF_ALO + c2 * 4, l);
                }
            }
        }

        CP_WAIT0();
        __syncthreads();

        // ---- MMA over nk k16-steps: hoisted loads, term-major de-chained ----
        for (int s = 0; s < nk; ++s) {
            const u32 sbyte = (u32)s * 32;
            u32 ah[2][4], al[2][4];
            #pragma unroll
            for (int mt = 0; mt < 2; ++mt) {
                u32 a = sb + aLB + (u32)mt * (16 * PITCH) + sbyte;
                ldm4(a + OF_AHI, ah[mt]);
                ldm4(a + OF_ALO, al[mt]);
            }
            u32 bh[2][4], bl[2][4];
            #pragma unroll
            for (int q = 0; q < 2; ++q) {
                u32 a = sb + bLB + (u32)q * (16 * PITCH) + sbyte;
                ldm4(a + OF_BHI, bh[q]);
                ldm4(a + OF_BLO, bl[q]);
            }
            // term 1: Ah * Bh — 8 distinct accumulators
            #pragma unroll
            for (int q = 0; q < 2; ++q)
                #pragma unroll
                for (int mt = 0; mt < 2; ++mt)
                    #pragma unroll
                    for (int h = 0; h < 2; ++h)
                        mma16816(acc[mt][q * 2 + h], ah[mt], &bh[q][2 * h]);
            // term 2: Ah * Bl
            #pragma unroll
            for (int q = 0; q < 2; ++q)
                #pragma unroll
                for (int mt = 0; mt < 2; ++mt)
                    #pragma unroll
                    for (int h = 0; h < 2; ++h)
                        mma16816(acc[mt][q * 2 + h], ah[mt], &bl[q][2 * h]);
            // term 3: Al * Bh
            #pragma unroll
            for (int q = 0; q < 2; ++q)
                #pragma unroll
                for (int mt = 0; mt < 2; ++mt)
                    #pragma unroll
                    for (int h = 0; h < 2; ++h)
                        mma16816(acc[mt][q * 2 + h], al[mt], &bh[q][2 * h]);
        }
    }

    // ---- epilogue: store partials ----
    const int r4 = lane >> 2, c4 = lane & 3;
    const int col0 = wn * 32;
    #pragma unroll
    for (int mt = 0; mt < 2; ++mt) {
        const size_t rg = (size_t)row0 + wm * 32 + mt * 16 + r4;
        float* base = &g_part[((size_t)ks * M_ALL + rg) * D_SZ + col0];
        #pragma unroll
        for (int nt = 0; nt < 4; ++nt) {
            float2 v0 = make_float2(acc[mt][nt][0], acc[mt][nt][1]);
            float2 v1 = make_float2(acc[mt][nt][2], acc[mt][nt][3]);
            *(float2*)(base + nt * 8 + c4 * 2)                    = v0;
            *(float2*)(base + 8 * (size_t)D_SZ + nt * 8 + c4 * 2) = v1;
        }
    }
}

// ---- K2: reduce k-slices + bias -> g_sup --------------------------------------
__global__ void reduce_kernel(const float* __restrict__ bias) {
    int idx = blockIdx.x * 256 + threadIdx.x;          // covers M_ALL*D exactly
    float s = bias[idx & 63];
    #pragma unroll
    for (int ks = 0; ks < KSPLIT; ++ks)
        s += g_part[(size_t)ks * M_ALL * D_SZ + idx];
    g_sup[idx] = s;
}

// ---- K3: warp-per-episode sims/softmax/preds/argmax/CE ------------------------
__global__ void sim_kernel(const float* __restrict__ onehot,
                           const int* __restrict__ tgty)
{
    const int b    = blockIdx.x;                    // 256 blocks, 32 threads
    const int lane = threadIdx.x;
    const unsigned FULL = 0xFFFFFFFFu;

    const float4* t4 = (const float4*)&g_sup[(size_t)(M_SUP + b) * D_SZ];
    float sim = -3.0e38f;
    if (lane < S_SZ) {
        const float4* s4 = (const float4*)&g_sup[(size_t)(b * S_SZ + lane) * D_SZ];
        float d0 = 0.f, d1 = 0.f, d2 = 0.f, d3 = 0.f;
        float m0 = 0.f, m1 = 0.f, m2 = 0.f, m3 = 0.f;
        #pragma unroll
        for (int i = 0; i < 16; ++i) {
            float4 s = s4[i], t = t4[i];
            d0 += s.x * t.x; d1 += s.y * t.y; d2 += s.z * t.z; d3 += s.w * t.w;
            m0 += s.x * s.x; m1 += s.y * s.y; m2 += s.z * s.z; m3 += s.w * s.w;
        }
        float dot = (d0 + d1) + (d2 + d3);
        float mag = (m0 + m1) + (m2 + m3);
        sim = dot * rsqrtf(fmaxf(mag, 1e-10f));
    }
    float m = sim;
    #pragma unroll
    for (int o = 16; o; o >>= 1) m = fmaxf(m, __shfl_xor_sync(FULL, m, o));
    float e = (lane < S_SZ) ? expf(sim - m) : 0.f;
    float sum = e;
    #pragma unroll
    for (int o = 16; o; o >>= 1) sum += __shfl_xor_sync(FULL, sum, o);
    float attn = e / sum;

    float p = 0.f;
    #pragma unroll
    for (int s = 0; s < S_SZ; ++s) {
        float a = __shfl_sync(FULL, attn, s);
        if (lane < C_SZ) p += a * onehot[((size_t)b * S_SZ + s) * C_SZ + lane];
    }

    float bv = (lane < C_SZ) ? p : -3.0e38f;
    int   bi = (lane < C_SZ) ? lane : 999;
    #pragma unroll
    for (int o = 16; o; o >>= 1) {
        float ov = __shfl_xor_sync(FULL, bv, o);
        int   oi = __shfl_xor_sync(FULL, bi, o);
        if (ov > bv || (ov == bv && oi < bi)) { bv = ov; bi = oi; }
    }
    float pm = (lane < C_SZ) ? p : -3.0e38f;
    #pragma unroll
    for (int o = 16; o; o >>= 1) pm = fmaxf(pm, __shfl_xor_sync(FULL, pm, o));
    float ee = (lane < C_SZ) ? expf(p - pm) : 0.f;
    float lse = ee;
    #pragma unroll
    for (int o = 16; o; o >>= 1) lse += __shfl_xor_sync(FULL, lse, o);

    int y = tgty[b];
    float py = __shfl_sync(FULL, p, y);
    if (lane == 0) {
        g_pb[b]        = (bi == y) ? 1.f : 0.f;
        g_pb[B_SZ + b] = -(py - pm - logf(lse));
    }
}

// ---- K4: deterministic final reduction -> d_out -------------------------------
__global__ void finalize_kernel(float* __restrict__ out) {
    __shared__ float sc[B_SZ], sl[B_SZ];
    int t = threadIdx.x;
    sc[t] = g_pb[t];
    sl[t] = g_pb[B_SZ + t];
    __syncthreads();
    for (int off = 128; off > 0; off >>= 1) {
        if (t < off) { sc[t] += sc[t + off]; sl[t] += sl[t + off]; }
        __syncthreads();
    }
    if (t == 0) {
        out[0] = sc[0] * (1.f / (float)B_SZ);
        out[1] = sl[0] * (1.f / (float)B_SZ);
    }
}

// ---------------------------------------------------------------------------
extern "C" void kernel_launch(void* const* d_in, const int* in_sizes, int n_in,
                              void* d_out, int out_size)
{
    const float* img    = (const float*)d_in[0];   // [256,20,20000]
    const float* onehot = (const float*)d_in[1];   // [256,20,20]
    const float* tgtim  = (const float*)d_in[2];   // [256,20000]
    const int*   tgty   = (const int*)  d_in[3];   // [256]
    const float* W      = (const float*)d_in[4];   // [64,20000]
    const float* bias   = (const float*)d_in[5];   // [64]
    float* out = (float*)d_out;                    // [2]

    cudaFuncSetAttribute(gemm_kernel,
                         cudaFuncAttributeMaxDynamicSharedMemorySize, SMEM_TOTAL);

    prep_w_kernel<<<(D_SZ * V_SZ) / 256, 256>>>(W);
    gemm_kernel<<<dim3(M_ALL / 128, KSPLIT), 256, SMEM_TOTAL>>>(img, tgtim);
    reduce_kernel<<<(M_ALL * D_SZ) / 256, 256>>>(bias);
    sim_kernel<<<B_SZ, 32>>>(onehot, tgty);
    finalize_kernel<<<1, B_SZ>>>(out);
}